// round 1
// baseline (speedup 1.0000x reference)
#include <cuda_runtime.h>
#include <cuda_bf16.h>

#define N_NODES 100000
#define N_EDGES 1600000
#define HID 64
#define DIN 128
#define NG 512
#define NC 10
#define SCAN_NBLK ((N_NODES + 511) / 512)

// ---------------- device scratch (no allocs allowed) ----------------
__device__ int   g_degE[N_NODES];        // in-degree (edges only)
__device__ int   g_off[N_NODES + 1];     // CSR row offsets (by dst)
__device__ int   g_cur[N_NODES];         // fill cursors
__device__ int   g_csr[N_EDGES];         // src indices grouped by dst
__device__ float g_dinv[N_NODES];        // rsqrt(deg+1)
__device__ float g_h[N_NODES * HID];     // pre-aggregation h
__device__ float g_ha[N_NODES * HID];    // post-aggregation h
__device__ float g_gsum[NG * HID];       // pooled sums
__device__ int   g_gcnt[NG];             // pooled counts
__device__ int   g_bsum[SCAN_NBLK];      // scan block sums

// ---------------- f32x2 packed FMA helpers ----------------
__device__ __forceinline__ void ffma2(unsigned long long& acc,
                                      unsigned long long a,
                                      unsigned long long b) {
    asm("fma.rn.f32x2 %0, %1, %2, %3;" : "=l"(acc) : "l"(a), "l"(b), "l"(acc));
}
__device__ __forceinline__ float2 upk(unsigned long long v) {
    float2 r;
    asm("mov.b64 {%0,%1}, %2;" : "=f"(r.x), "=f"(r.y) : "l"(v));
    return r;
}

// ---------------- init: zero scratch ----------------
__global__ void k_init() {
    int i = blockIdx.x * blockDim.x + threadIdx.x;
    int stride = gridDim.x * blockDim.x;
    for (int j = i; j < N_NODES; j += stride) g_degE[j] = 0;
    for (int j = i; j < NG * HID; j += stride) g_gsum[j] = 0.f;
    for (int j = i; j < NG; j += stride) g_gcnt[j] = 0;
}

// ---------------- degree count ----------------
__global__ void k_deg(const int* __restrict__ ei) {
    int e = blockIdx.x * blockDim.x + threadIdx.x;
    if (e >= N_EDGES) return;
    atomicAdd(&g_degE[ei[N_EDGES + e]], 1);
}

// ---------------- dinv ----------------
__global__ void k_dinv() {
    int i = blockIdx.x * blockDim.x + threadIdx.x;
    if (i >= N_NODES) return;
    g_dinv[i] = rsqrtf((float)g_degE[i] + 1.0f);
}

// ---------------- scan stage 1: per-block sums (512 elems / block) ----------------
__global__ void k_scan1() {
    __shared__ int sh[256];
    int b = blockIdx.x, t = threadIdx.x;
    int base = b * 512;
    int v = 0;
    int i0 = base + t, i1 = base + 256 + t;
    if (i0 < N_NODES) v += g_degE[i0];
    if (i1 < N_NODES) v += g_degE[i1];
    sh[t] = v;
    __syncthreads();
    for (int o = 128; o > 0; o >>= 1) {
        if (t < o) sh[t] += sh[t + o];
        __syncthreads();
    }
    if (t == 0) g_bsum[b] = sh[0];
}

// ---------------- scan stage 2: top-level exclusive scan ----------------
__global__ void k_scan2() {
    if (threadIdx.x == 0 && blockIdx.x == 0) {
        int acc = 0;
        for (int b = 0; b < SCAN_NBLK; b++) {
            int s = g_bsum[b];
            g_bsum[b] = acc;
            acc += s;
        }
        g_off[N_NODES] = acc;  // == N_EDGES
    }
}

// ---------------- scan stage 3: block-local exclusive scan + write offsets ----------------
__global__ void k_scan3() {
    __shared__ int sh[512];
    int b = blockIdx.x, t = threadIdx.x;
    int i = b * 512 + t;
    int v = (i < N_NODES) ? g_degE[i] : 0;
    sh[t] = v;
    __syncthreads();
    for (int off = 1; off < 512; off <<= 1) {
        int tmp = (t >= off) ? sh[t - off] : 0;
        __syncthreads();
        sh[t] += tmp;
        __syncthreads();
    }
    if (i < N_NODES) {
        int excl = sh[t] - v + g_bsum[b];
        g_off[i] = excl;
        g_cur[i] = excl;
    }
}

// ---------------- CSR fill ----------------
__global__ void k_fill(const int* __restrict__ ei) {
    int e = blockIdx.x * blockDim.x + threadIdx.x;
    if (e >= N_EDGES) return;
    int s = ei[e], d = ei[N_EDGES + e];
    int p = atomicAdd(&g_cur[d], 1);
    g_csr[p] = s;
}

// ---------------- GEMM: Y[N,64] = X[N,K] @ W[K,64], f32x2 packed ----------------
// 16 nodes / block, warp handles 2 nodes, lane handles channels (lane, lane+32)
template <int K>
__global__ void k_gemm(const float* __restrict__ X, const float* __restrict__ W,
                       float* __restrict__ Y) {
    constexpr int KP = K / 2;
    constexpr int PITCH2 = KP + 1;  // float2 pitch (8B pad per row, conflict-free)
    __shared__ float2 Wt2[64 * PITCH2];  // W transposed: [c][k-pairs]
    __shared__ float xs[16 * K];
    int tid = threadIdx.x;

    // load W transposed into padded smem
    for (int idx = tid; idx < K * 64; idx += 256) {
        int k = idx >> 6, c = idx & 63;
        ((float*)Wt2)[c * (2 * PITCH2) + k] = W[idx];
    }
    // load x tile (vectorized)
    int nb = blockIdx.x * 16;
    const float4* Xv = (const float4*)(X + (size_t)nb * K);
    float4* xsv = (float4*)xs;
    for (int idx = tid; idx < 16 * K / 4; idx += 256) xsv[idx] = Xv[idx];
    __syncthreads();

    int warp = tid >> 5, lane = tid & 31;
    int j0 = warp * 2;
    unsigned long long a00 = 0, a01 = 0, a10 = 0, a11 = 0;
    const unsigned long long* w0p = (const unsigned long long*)(Wt2 + lane * PITCH2);
    const unsigned long long* w1p = (const unsigned long long*)(Wt2 + (lane + 32) * PITCH2);
    const unsigned long long* x0p = (const unsigned long long*)(xs + (size_t)j0 * K);
    const unsigned long long* x1p = (const unsigned long long*)(xs + (size_t)(j0 + 1) * K);

#pragma unroll 8
    for (int kp = 0; kp < KP; kp++) {
        unsigned long long w0 = w0p[kp];
        unsigned long long w1 = w1p[kp];
        unsigned long long xa = x0p[kp];
        unsigned long long xb = x1p[kp];
        ffma2(a00, xa, w0);
        ffma2(a01, xa, w1);
        ffma2(a10, xb, w0);
        ffma2(a11, xb, w1);
    }
    float2 v;
    int n0 = nb + j0;
    v = upk(a00); Y[(size_t)n0 * 64 + lane] = v.x + v.y;
    v = upk(a01); Y[(size_t)n0 * 64 + lane + 32] = v.x + v.y;
    v = upk(a10); Y[(size_t)(n0 + 1) * 64 + lane] = v.x + v.y;
    v = upk(a11); Y[(size_t)(n0 + 1) * 64 + lane + 32] = v.x + v.y;
}

// ---------------- gather-aggregate + self-loop + bias + relu ----------------
// one warp per destination node; lane covers channels (lane, lane+32)
__global__ void k_gather(const float* __restrict__ hin, float* __restrict__ hout,
                         const float* __restrict__ bias) {
    int v = (blockIdx.x * blockDim.x + threadIdx.x) >> 5;
    int lane = threadIdx.x & 31;
    if (v >= N_NODES) return;
    float dv = g_dinv[v];
    int e0 = g_off[v], e1 = g_off[v + 1];
    float a0 = 0.f, a1 = 0.f;
#pragma unroll 2
    for (int e = e0; e < e1; e++) {
        int s = g_csr[e];
        float c = g_dinv[s] * dv;
        const float* hr = hin + (size_t)s * 64;
        a0 += c * hr[lane];
        a1 += c * hr[lane + 32];
    }
    float sl = dv * dv;
    const float* hv = hin + (size_t)v * 64;
    a0 += sl * hv[lane];
    a1 += sl * hv[lane + 32];
    a0 = fmaxf(a0 + bias[lane], 0.f);
    a1 = fmaxf(a1 + bias[lane + 32], 0.f);
    float* o = hout + (size_t)v * 64;
    o[lane] = a0;
    o[lane + 32] = a1;
}

// ---------------- pooling: exploit sorted batch; smem pre-reduce per block ----------------
#define POOL_SPAN 24
__global__ void k_pool(const float* __restrict__ h, const int* __restrict__ batch) {
    __shared__ int bs[256];
    __shared__ float ssum[POOL_SPAN * 64];
    __shared__ int scnt[POOL_SPAN];
    int t = threadIdx.x;
    int base = blockIdx.x * 256;
    int n = N_NODES - base;
    if (n > 256) n = 256;
    bs[t] = (t < n) ? batch[base + t] : -1;
    __syncthreads();
    int g0 = bs[0];
    int gmax = bs[n - 1];
    int span = gmax - g0 + 1;
    int c = t & 63, rg = t >> 6;
    if (span <= POOL_SPAN) {
        for (int idx = t; idx < POOL_SPAN * 64; idx += 256) ssum[idx] = 0.f;
        if (t < POOL_SPAN) scnt[t] = 0;
        __syncthreads();
        for (int k = rg; k < n; k += 4) {
            int g = bs[k] - g0;
            atomicAdd(&ssum[g * 64 + c], h[(size_t)(base + k) * 64 + c]);
        }
        if (t < n) atomicAdd(&scnt[bs[t] - g0], 1);
        __syncthreads();
        for (int idx = t; idx < span * 64; idx += 256)
            atomicAdd(&g_gsum[(g0 + (idx >> 6)) * 64 + (idx & 63)], ssum[idx]);
        if (t < span) atomicAdd(&g_gcnt[g0 + t], scnt[t]);
    } else {
        for (int k = rg; k < n; k += 4)
            atomicAdd(&g_gsum[bs[k] * 64 + c], h[(size_t)(base + k) * 64 + c]);
        if (t < n) atomicAdd(&g_gcnt[bs[t]], 1);
    }
}

// ---------------- head: mean, FC, log_softmax. one warp per graph ----------------
__global__ void k_head(const float* __restrict__ Wfc, const float* __restrict__ bfc,
                       float* __restrict__ out) {
    int g = (blockIdx.x * blockDim.x + threadIdx.x) >> 5;
    int lane = threadIdx.x & 31;
    if (g >= NG) return;
    float cnt = (float)g_gcnt[g];
    float inv = 1.0f / fmaxf(cnt, 1.0f);
    float p0 = g_gsum[g * 64 + lane] * inv;
    float p1 = g_gsum[g * 64 + 32 + lane] * inv;
    float l[NC];
#pragma unroll
    for (int j = 0; j < NC; j++) {
        float part = p0 * Wfc[lane * NC + j] + p1 * Wfc[(lane + 32) * NC + j];
#pragma unroll
        for (int o = 16; o; o >>= 1) part += __shfl_xor_sync(0xffffffffu, part, o);
        l[j] = part + bfc[j];
    }
    float m = l[0];
#pragma unroll
    for (int j = 1; j < NC; j++) m = fmaxf(m, l[j]);
    float s = 0.f;
#pragma unroll
    for (int j = 0; j < NC; j++) s += expf(l[j] - m);
    float lse = m + logf(s);
    if (lane < NC) out[g * NC + lane] = l[lane] - lse;
}

// ---------------- launch ----------------
extern "C" void kernel_launch(void* const* d_in, const int* in_sizes, int n_in,
                              void* d_out, int out_size) {
    const float* x   = (const float*)d_in[0];
    const int*   ei  = (const int*)d_in[1];
    const int*   bat = (const int*)d_in[2];
    const float* W1  = (const float*)d_in[3];
    const float* b1  = (const float*)d_in[4];
    const float* W2  = (const float*)d_in[5];
    const float* b2  = (const float*)d_in[6];
    const float* Wfc = (const float*)d_in[7];
    const float* bfc = (const float*)d_in[8];
    float* out = (float*)d_out;

    k_init<<<256, 256>>>();
    k_deg<<<(N_EDGES + 255) / 256, 256>>>(ei);
    k_dinv<<<(N_NODES + 255) / 256, 256>>>();
    k_scan1<<<SCAN_NBLK, 256>>>();
    k_scan2<<<1, 32>>>();
    k_scan3<<<SCAN_NBLK, 512>>>();
    k_fill<<<(N_EDGES + 255) / 256, 256>>>(ei);

    // layer 1
    k_gemm<DIN><<<N_NODES / 16, 256>>>(x, W1, g_h);
    k_gather<<<(N_NODES * 32 + 255) / 256, 256>>>(g_h, g_ha, b1);
    // layer 2
    k_gemm<HID><<<N_NODES / 16, 256>>>(g_ha, W2, g_h);
    k_gather<<<(N_NODES * 32 + 255) / 256, 256>>>(g_h, g_ha, b2);
    // pool + head
    k_pool<<<(N_NODES + 255) / 256, 256>>>(g_ha, bat);
    k_head<<<(NG + 7) / 8, 256>>>(Wfc, bfc, out);
}

// round 3
// speedup vs baseline: 1.0927x; 1.0927x over previous
#include <cuda_runtime.h>
#include <cuda_bf16.h>

#define N_NODES 100000
#define N_EDGES 1600000
#define HID 64
#define DIN 128
#define NG 512
#define NC 10
#define SCAN_NBLK ((N_NODES + 511) / 512)

typedef unsigned long long ull;

// ---------------- device scratch ----------------
__device__ int   g_degE[N_NODES];
__device__ int   g_off[N_NODES + 1];
__device__ int   g_cur[N_NODES];
__device__ int   g_csr[N_EDGES];
__device__ float g_coef[N_EDGES];
__device__ float g_dinv[N_NODES];
__device__ float g_h[N_NODES * HID];
__device__ float g_ha[N_NODES * HID];
__device__ float g_gsum[NG * HID];
__device__ int   g_gcnt[NG];
__device__ int   g_bsum[SCAN_NBLK];

// ---------------- f32x2 helpers ----------------
__device__ __forceinline__ void ffma2(ull& acc, ull a, ull b) {
    asm("fma.rn.f32x2 %0, %1, %2, %3;" : "=l"(acc) : "l"(a), "l"(b), "l"(acc));
}
__device__ __forceinline__ float2 upk(ull v) {
    float2 r;
    asm("mov.b64 {%0,%1}, %2;" : "=f"(r.x), "=f"(r.y) : "l"(v));
    return r;
}

// ---------------- init ----------------
__global__ void k_init() {
    int i = blockIdx.x * blockDim.x + threadIdx.x;
    int stride = gridDim.x * blockDim.x;
    for (int j = i; j < N_NODES; j += stride) g_degE[j] = 0;
    for (int j = i; j < NG * HID; j += stride) g_gsum[j] = 0.f;
    for (int j = i; j < NG; j += stride) g_gcnt[j] = 0;
}

// ---------------- degree ----------------
__global__ void k_deg(const int* __restrict__ ei) {
    int e = blockIdx.x * blockDim.x + threadIdx.x;
    if (e >= N_EDGES) return;
    atomicAdd(&g_degE[ei[N_EDGES + e]], 1);
}

// ---------------- scan stage 1 ----------------
__global__ void k_scan1() {
    __shared__ int sh[256];
    int b = blockIdx.x, t = threadIdx.x;
    int base = b * 512;
    int v = 0;
    int i0 = base + t, i1 = base + 256 + t;
    if (i0 < N_NODES) v += g_degE[i0];
    if (i1 < N_NODES) v += g_degE[i1];
    sh[t] = v;
    __syncthreads();
    for (int o = 128; o > 0; o >>= 1) {
        if (t < o) sh[t] += sh[t + o];
        __syncthreads();
    }
    if (t == 0) g_bsum[b] = sh[0];
}

// ---------------- scan stage 2: parallel block-sum scan (1 block) ----------------
__global__ void k_scan2() {
    __shared__ int sh[256];
    int t = threadIdx.x;
    int v = (t < SCAN_NBLK) ? g_bsum[t] : 0;
    sh[t] = v;
    __syncthreads();
    for (int off = 1; off < 256; off <<= 1) {
        int tmp = (t >= off) ? sh[t - off] : 0;
        __syncthreads();
        sh[t] += tmp;
        __syncthreads();
    }
    if (t < SCAN_NBLK) g_bsum[t] = sh[t] - v;  // exclusive
    if (t == 255) g_off[N_NODES] = sh[255];
}

// ---------------- scan stage 3 + dinv ----------------
__global__ void k_scan3() {
    __shared__ int sh[512];
    int b = blockIdx.x, t = threadIdx.x;
    int i = b * 512 + t;
    int v = (i < N_NODES) ? g_degE[i] : 0;
    sh[t] = v;
    __syncthreads();
    for (int off = 1; off < 512; off <<= 1) {
        int tmp = (t >= off) ? sh[t - off] : 0;
        __syncthreads();
        sh[t] += tmp;
        __syncthreads();
    }
    if (i < N_NODES) {
        int excl = sh[t] - v + g_bsum[b];
        g_off[i] = excl;
        g_cur[i] = excl;
        g_dinv[i] = rsqrtf((float)v + 1.0f);
    }
}

// ---------------- CSR fill + per-edge coefficient ----------------
__global__ void k_fill(const int* __restrict__ ei) {
    int e = blockIdx.x * blockDim.x + threadIdx.x;
    if (e >= N_EDGES) return;
    int s = ei[e], d = ei[N_EDGES + e];
    int p = atomicAdd(&g_cur[d], 1);
    g_csr[p] = s;
    g_coef[p] = g_dinv[s] * g_dinv[d];
}

// ---------------- GEMM: Y[N,64] = X[N,K] @ W[K,64] ----------------
// 32 nodes/block, 8 warps, 4 nodes/warp; lane covers channels (lane, lane+32)
// Wt layout [kp][64] float2 -> consecutive-lane LDS.64, conflict-free
template <int K>
__global__ void __launch_bounds__(256) k_gemm(const float* __restrict__ X,
                                              const float* __restrict__ W,
                                              float* __restrict__ Y, int nNodes) {
    constexpr int KP = K / 2;
    __shared__ float2 Wt[KP * 64];       // K=128: 32KB
    __shared__ float2 xs[32 * KP];       // K=128: 16KB
    int tid = threadIdx.x;

    for (int idx = tid; idx < KP * 64; idx += 256) {
        int kp = idx >> 6, c = idx & 63;
        Wt[idx] = make_float2(W[(2 * kp) * 64 + c], W[(2 * kp + 1) * 64 + c]);
    }
    int nb = blockIdx.x * 32;
    int nvalid = nNodes - nb;
    if (nvalid > 32) nvalid = 32;
    const float2* Xv = (const float2*)(X + (size_t)nb * K);
    for (int idx = tid; idx < 32 * KP; idx += 256)
        xs[idx] = (idx < nvalid * KP) ? Xv[idx] : make_float2(0.f, 0.f);
    __syncthreads();

    int warp = tid >> 5, lane = tid & 31;
    int j0 = warp * 4;
    ull acc[4][2];
#pragma unroll
    for (int j = 0; j < 4; j++) acc[j][0] = acc[j][1] = 0ull;

    const ull* wp = (const ull*)Wt;
    const ull* xp = (const ull*)(xs + j0 * KP);
#pragma unroll 4
    for (int kp = 0; kp < KP; kp++) {
        ull w0 = wp[kp * 64 + lane];
        ull w1 = wp[kp * 64 + lane + 32];
#pragma unroll
        for (int j = 0; j < 4; j++) {
            ull xj = xp[j * KP + kp];
            ffma2(acc[j][0], xj, w0);
            ffma2(acc[j][1], xj, w1);
        }
    }
#pragma unroll
    for (int j = 0; j < 4; j++) {
        int n = nb + j0 + j;
        if (n < nNodes) {
            float2 v0 = upk(acc[j][0]);
            float2 v1 = upk(acc[j][1]);
            Y[(size_t)n * 64 + lane] = v0.x + v0.y;
            Y[(size_t)n * 64 + lane + 32] = v1.x + v1.y;
        }
    }
}

// ---------------- gather + self-loop + bias + relu ----------------
// warp per node; lane covers a float2 (channels 2*lane, 2*lane+1)
__global__ void k_gather(const float* __restrict__ hin, float* __restrict__ hout,
                         const float* __restrict__ bias) {
    int v = (blockIdx.x * blockDim.x + threadIdx.x) >> 5;
    int lane = threadIdx.x & 31;
    if (v >= N_NODES) return;
    int e0 = g_off[v], e1 = g_off[v + 1];
    const float2* H = (const float2*)hin;
    float ax = 0.f, ay = 0.f;
    int e = e0;
    for (; e + 4 <= e1; e += 4) {
        int s0 = g_csr[e], s1 = g_csr[e + 1], s2 = g_csr[e + 2], s3 = g_csr[e + 3];
        float c0 = g_coef[e], c1 = g_coef[e + 1], c2 = g_coef[e + 2], c3 = g_coef[e + 3];
        float2 h0 = H[(size_t)s0 * 32 + lane];
        float2 h1 = H[(size_t)s1 * 32 + lane];
        float2 h2 = H[(size_t)s2 * 32 + lane];
        float2 h3 = H[(size_t)s3 * 32 + lane];
        ax = fmaf(c0, h0.x, ax); ay = fmaf(c0, h0.y, ay);
        ax = fmaf(c1, h1.x, ax); ay = fmaf(c1, h1.y, ay);
        ax = fmaf(c2, h2.x, ax); ay = fmaf(c2, h2.y, ay);
        ax = fmaf(c3, h3.x, ax); ay = fmaf(c3, h3.y, ay);
    }
    for (; e < e1; e++) {
        int s = g_csr[e];
        float c = g_coef[e];
        float2 h = H[(size_t)s * 32 + lane];
        ax = fmaf(c, h.x, ax); ay = fmaf(c, h.y, ay);
    }
    float dv = g_dinv[v];
    float sl = dv * dv;
    float2 hv = H[(size_t)v * 32 + lane];
    ax = fmaf(sl, hv.x, ax); ay = fmaf(sl, hv.y, ay);
    float2 b2 = ((const float2*)bias)[lane];
    float2 o;
    o.x = fmaxf(ax + b2.x, 0.f);
    o.y = fmaxf(ay + b2.y, 0.f);
    ((float2*)hout)[(size_t)v * 32 + lane] = o;
}

// ---------------- pooling ----------------
#define POOL_SPAN 24
__global__ void k_pool(const float* __restrict__ h, const int* __restrict__ batch) {
    __shared__ int bs[256];
    __shared__ float ssum[POOL_SPAN * 64];
    __shared__ int scnt[POOL_SPAN];
    int t = threadIdx.x;
    int base = blockIdx.x * 256;
    int n = N_NODES - base;
    if (n > 256) n = 256;
    bs[t] = (t < n) ? batch[base + t] : -1;
    __syncthreads();
    int g0 = bs[0];
    int gmax = bs[n - 1];
    int span = gmax - g0 + 1;
    int c = t & 63, rg = t >> 6;
    if (span <= POOL_SPAN) {
        for (int idx = t; idx < POOL_SPAN * 64; idx += 256) ssum[idx] = 0.f;
        if (t < POOL_SPAN) scnt[t] = 0;
        __syncthreads();
        for (int k = rg; k < n; k += 4) {
            int g = bs[k] - g0;
            atomicAdd(&ssum[g * 64 + c], h[(size_t)(base + k) * 64 + c]);
        }
        if (t < n) atomicAdd(&scnt[bs[t] - g0], 1);
        __syncthreads();
        for (int idx = t; idx < span * 64; idx += 256)
            atomicAdd(&g_gsum[(g0 + (idx >> 6)) * 64 + (idx & 63)], ssum[idx]);
        if (t < span) atomicAdd(&g_gcnt[g0 + t], scnt[t]);
    } else {
        for (int k = rg; k < n; k += 4)
            atomicAdd(&g_gsum[bs[k] * 64 + c], h[(size_t)(base + k) * 64 + c]);
        if (t < n) atomicAdd(&g_gcnt[bs[t]], 1);
    }
}

// ---------------- head ----------------
__global__ void k_head(const float* __restrict__ Wfc, const float* __restrict__ bfc,
                       float* __restrict__ out) {
    int g = (blockIdx.x * blockDim.x + threadIdx.x) >> 5;
    int lane = threadIdx.x & 31;
    if (g >= NG) return;
    float cnt = (float)g_gcnt[g];
    float inv = 1.0f / fmaxf(cnt, 1.0f);
    float p0 = g_gsum[g * 64 + lane] * inv;
    float p1 = g_gsum[g * 64 + 32 + lane] * inv;
    float l[NC];
#pragma unroll
    for (int j = 0; j < NC; j++) {
        float part = p0 * Wfc[lane * NC + j] + p1 * Wfc[(lane + 32) * NC + j];
#pragma unroll
        for (int o = 16; o; o >>= 1) part += __shfl_xor_sync(0xffffffffu, part, o);
        l[j] = part + bfc[j];
    }
    float m = l[0];
#pragma unroll
    for (int j = 1; j < NC; j++) m = fmaxf(m, l[j]);
    float s = 0.f;
#pragma unroll
    for (int j = 0; j < NC; j++) s += expf(l[j] - m);
    float lse = m + logf(s);
    if (lane < NC) out[g * NC + lane] = l[lane] - lse;
}

// ---------------- launch ----------------
extern "C" void kernel_launch(void* const* d_in, const int* in_sizes, int n_in,
                              void* d_out, int out_size) {
    const float* x   = (const float*)d_in[0];
    const int*   ei  = (const int*)d_in[1];
    const int*   bat = (const int*)d_in[2];
    const float* W1  = (const float*)d_in[3];
    const float* b1  = (const float*)d_in[4];
    const float* W2  = (const float*)d_in[5];
    const float* b2  = (const float*)d_in[6];
    const float* Wfc = (const float*)d_in[7];
    const float* bfc = (const float*)d_in[8];
    float* out = (float*)d_out;

    k_init<<<256, 256>>>();
    k_deg<<<(N_EDGES + 255) / 256, 256>>>(ei);
    k_scan1<<<SCAN_NBLK, 256>>>();
    k_scan2<<<1, 256>>>();
    k_scan3<<<SCAN_NBLK, 512>>>();
    k_fill<<<(N_EDGES + 255) / 256, 256>>>(ei);

    k_gemm<DIN><<<(N_NODES + 31) / 32, 256>>>(x, W1, g_h, N_NODES);
    k_gather<<<(N_NODES * 32 + 255) / 256, 256>>>(g_h, g_ha, b1);
    k_gemm<HID><<<(N_NODES + 31) / 32, 256>>>(g_ha, W2, g_h, N_NODES);
    k_gather<<<(N_NODES * 32 + 255) / 256, 256>>>(g_h, g_ha, b2);
    k_pool<<<(N_NODES + 255) / 256, 256>>>(g_ha, bat);
    k_head<<<(NG + 7) / 8, 256>>>(Wfc, bfc, out);
}